// round 5
// baseline (speedup 1.0000x reference)
#include <cuda_runtime.h>
#include <math.h>

#define TT 512
#define BB 64
#define II 512
#define HH 512
#define NCTA2 128

// Global-barrier counter for the persistent phase-2 kernel.
// Reset to 0 via cudaMemsetAsync at every kernel_launch (graph-capturable).
__device__ unsigned int g_bar;

// ---------------------------------------------------------------------------
// Phase 1: C[M=T*B, N=H] = X[M,K] @ W[N,K]^T + (b_ih + b_hh)
// 128x64 block tile, K-tile 16, 256 threads, 8x4 per-thread register tile.
// ---------------------------------------------------------------------------
__global__ __launch_bounds__(256) void gemm_xproj(
    const float* __restrict__ X, const float* __restrict__ W,
    const float* __restrict__ bih, const float* __restrict__ bhh,
    float* __restrict__ C)
{
    __shared__ float As[16][132];  // row stride 132 floats = 528B (16B aligned)
    __shared__ float Bs[16][68];   // 272B rows

    const int bm  = blockIdx.x;    // 0..255  (M tiles of 128)
    const int bn  = blockIdx.y;    // 0..7    (N tiles of 64)
    const int tid = threadIdx.x;
    const int tx  = tid & 15;      // 16 threads cover 64 cols (4 each)
    const int ty  = tid >> 4;      // 16 threads cover 128 rows (8 each)

    const int arow0 = bm * 128;
    const int brow0 = bn * 64;

    float acc[8][4];
#pragma unroll
    for (int i = 0; i < 8; i++)
#pragma unroll
        for (int j = 0; j < 4; j++) acc[i][j] = 0.0f;

    for (int kt = 0; kt < II; kt += 16) {
        // Stage A: 128 rows x 16 k  (512 float4 loads, transposed into smem)
#pragma unroll
        for (int i = 0; i < 2; i++) {
            int idx = tid + i * 256;
            int row = idx >> 2;
            int kq  = idx & 3;
            float4 v = *(const float4*)(X + (size_t)(arow0 + row) * II + kt + kq * 4);
            As[kq * 4 + 0][row] = v.x;
            As[kq * 4 + 1][row] = v.y;
            As[kq * 4 + 2][row] = v.z;
            As[kq * 4 + 3][row] = v.w;
        }
        // Stage B: 64 rows x 16 k (256 float4 loads)
        {
            int row = tid >> 2;
            int kq  = tid & 3;
            float4 v = *(const float4*)(W + (size_t)(brow0 + row) * II + kt + kq * 4);
            Bs[kq * 4 + 0][row] = v.x;
            Bs[kq * 4 + 1][row] = v.y;
            Bs[kq * 4 + 2][row] = v.z;
            Bs[kq * 4 + 3][row] = v.w;
        }
        __syncthreads();

#pragma unroll
        for (int k = 0; k < 16; k++) {
            float4 a0 = *(const float4*)&As[k][ty * 8];
            float4 a1 = *(const float4*)&As[k][ty * 8 + 4];
            float4 bv = *(const float4*)&Bs[k][tx * 4];
            float a[8] = {a0.x, a0.y, a0.z, a0.w, a1.x, a1.y, a1.z, a1.w};
            float b4[4] = {bv.x, bv.y, bv.z, bv.w};
#pragma unroll
            for (int i = 0; i < 8; i++)
#pragma unroll
                for (int j = 0; j < 4; j++)
                    acc[i][j] = fmaf(a[i], b4[j], acc[i][j]);
        }
        __syncthreads();
    }

    // Epilogue: add fused bias, vectorized store
    float4 bias;
    {
        int n = brow0 + tx * 4;
        bias.x = bih[n + 0] + bhh[n + 0];
        bias.y = bih[n + 1] + bhh[n + 1];
        bias.z = bih[n + 2] + bhh[n + 2];
        bias.w = bih[n + 3] + bhh[n + 3];
    }
#pragma unroll
    for (int i = 0; i < 8; i++) {
        int m = arow0 + ty * 8 + i;
        float4 o = make_float4(acc[i][0] + bias.x, acc[i][1] + bias.y,
                               acc[i][2] + bias.z, acc[i][3] + bias.w);
        *(float4*)(C + (size_t)m * HH + brow0 + tx * 4) = o;
    }
}

// ---------------------------------------------------------------------------
// Phase 2: persistent recurrence kernel. 128 CTAs, 256 threads each.
// CTA c owns output columns [4c, 4c+4); its W_hh slice lives in smem for all
// 512 steps. Thread (b = tid>>2, jl = tid&3) computes one output element per
// step. Global sync via monotonic counter barrier.
// out[] doubles as xproj (input) and output (overwritten in place).
// ---------------------------------------------------------------------------
__global__ __launch_bounds__(256, 1) void rnn_steps(
    const float* __restrict__ Whh, float* __restrict__ out,
    unsigned int* __restrict__ bar)
{
    __shared__ float ws[4][520];   // padded: 520 % 32 = 8 -> conflict-free j-quad

    const int cta = blockIdx.x;
    const int tid = threadIdx.x;
    const int b   = tid >> 2;          // 0..63
    const int jl  = tid & 3;           // 0..3
    const int j   = cta * 4 + jl;      // global column

    // Load W_hh slice (4 rows x 512) once; resident for all steps.
    for (int i = tid; i < 4 * (HH / 4); i += 256) {
        int r  = i >> 7;          // 0..3
        int kq = i & 127;         // float4 index within row
        float4 v = *(const float4*)(Whh + (size_t)(cta * 4 + r) * HH + kq * 4);
        *(float4*)&ws[r][kq * 4] = v;
    }
    __syncthreads();

    const float* wrow = ws[jl];

    // t = 0: h0 = 0, so h = tanh(xproj)
    float h = tanhf(out[(size_t)b * HH + j]);
    out[(size_t)b * HH + j] = h;
    __threadfence();
    __syncthreads();
    if (tid == 0)
        asm volatile("red.release.gpu.global.add.u32 [%0], 1;" :: "l"(bar) : "memory");

    for (int t = 1; t < TT; t++) {
        // Wait until all CTAs finished step t-1 (counter reaches t*NCTA2)
        if (tid == 0) {
            unsigned int v;
            const unsigned int target = (unsigned int)t * NCTA2;
            do {
                asm volatile("ld.acquire.gpu.global.u32 %0, [%1];"
                             : "=r"(v) : "l"(bar) : "memory");
            } while (v < target);
        }
        __syncthreads();

        const float* hprev = out + (size_t)(t - 1) * BB * HH + (size_t)b * HH;
        float xp = out[((size_t)t * BB + b) * HH + j];

        // 4 split accumulators -> dependent-chain length 128 (not 512)
        float a0 = xp, a1 = 0.0f, a2 = 0.0f, a3 = 0.0f;
#pragma unroll 8
        for (int k4 = 0; k4 < HH / 4; k4++) {
            float4 hv = *(const float4*)(hprev + k4 * 4);
            float4 wv = *(const float4*)(wrow + k4 * 4);
            a0 = fmaf(hv.x, wv.x, a0);
            a1 = fmaf(hv.y, wv.y, a1);
            a2 = fmaf(hv.z, wv.z, a2);
            a3 = fmaf(hv.w, wv.w, a3);
        }
        h = tanhf((a0 + a1) + (a2 + a3));
        out[((size_t)t * BB + b) * HH + j] = h;

        __threadfence();
        __syncthreads();
        if (tid == 0)
            asm volatile("red.release.gpu.global.add.u32 [%0], 1;" :: "l"(bar) : "memory");
    }

    // h_n tail: each thread still holds its t = T-1 value in a register.
    out[(size_t)TT * BB * HH + (size_t)b * HH + j] = h;
}

// ---------------------------------------------------------------------------
// Launch
// Inputs (metadata order): x [T,B,I], w_ih [H,I], w_hh [H,H], b_ih [H], b_hh [H]
// Output: output [T,B,H] followed by h_n [B,H]  (fp32)
// ---------------------------------------------------------------------------
extern "C" void kernel_launch(void* const* d_in, const int* in_sizes, int n_in,
                              void* d_out, int out_size)
{
    (void)in_sizes; (void)n_in; (void)out_size;
    const float* x    = (const float*)d_in[0];
    const float* w_ih = (const float*)d_in[1];
    const float* w_hh = (const float*)d_in[2];
    const float* b_ih = (const float*)d_in[3];
    const float* b_hh = (const float*)d_in[4];
    float* out = (float*)d_out;

    // Reset the global barrier counter (graph-capturable memset node).
    void* bar_ptr = nullptr;
    cudaGetSymbolAddress(&bar_ptr, g_bar);
    cudaMemsetAsync(bar_ptr, 0, sizeof(unsigned int));

    // Phase 1: xproj into d_out
    dim3 g1((TT * BB) / 128, HH / 64);
    gemm_xproj<<<g1, 256>>>(x, w_ih, b_ih, b_hh, out);

    // Phase 2: persistent recurrence
    rnn_steps<<<NCTA2, 256>>>(w_hh, out, (unsigned int*)bar_ptr);
}